// round 3
// baseline (speedup 1.0000x reference)
#include <cuda_runtime.h>
#include <cstdint>

#define B_    8
#define S_    4096
#define D_    1024
#define L_    16

// ---- kernel A geometry ----
#define ABLK  128          // 32768 s-rows / 256
#define AROWS 256          // s-rows per block (rows t and t+128 per thread)
#define ATHR  128
#define DC    64           // d-chunk width
#define NCH   (D_/DC)      // 16 chunks
#define PITCH 68           // padded floats per tile row (16B aligned, conflict-free)
#define TILEF (AROWS*PITCH)         // 17408 floats per buffer
#define OFF_WR (2*TILEF)
#define SMEMA_BYTES ((OFF_WR + 4*L_) * 4)   // ~139 KB

// ---- kernel C geometry ----
#define CBLK  256          // 2 CTAs/SM
#define CROWS 128

__constant__ __align__(16) float c_summ[L_*D_];   // 64 KB, fed by D2D memcpy

// device scratch (allocation-free rule)
__device__ float g_e[B_*L_*S_];        // exp(scores)   2 MB
__device__ float g_zpart[ABLK*L_];     // per-A-block partial Z
__device__ float g_part[CBLK*D_];      // per-C-block partial ctx
__device__ int   g_cnt[B_];            // arrival counters (reset by kernel A)

__device__ __forceinline__ unsigned long long ffma2(unsigned long long a,
                                                    unsigned long long b,
                                                    unsigned long long c) {
    unsigned long long d;
    asm("fma.rn.f32x2 %0, %1, %2, %3;" : "=l"(d) : "l"(a), "l"(b), "l"(c));
    return d;
}

__device__ __forceinline__ void cpa16(uint32_t saddr, const void* gaddr) {
    asm volatile("cp.async.ca.shared.global [%0], [%1], 16;\n" :: "r"(saddr), "l"(gaddr));
}

// ---------------------------------------------------------------------------
// Kernel A: e[b,l,s] = exp( dot(summ[l], mem[b,s]) / 32 )  + per-block Z partials
// summarizer comes from the constant port (LDC.128); m tile double-buffered
// through smem via cp.async; K packed into f32x2 FMAs.
// ---------------------------------------------------------------------------
__global__ void __launch_bounds__(ATHR, 1)
kA(const float* __restrict__ mem) {
    extern __shared__ float sA[];
    const int t   = threadIdx.x;
    const int bx  = blockIdx.x;
    const uint32_t sbase = (uint32_t)__cvta_generic_to_shared(sA);

    if (bx < B_ && t == 0) g_cnt[bx] = 0;     // reset kernel-C counters each launch

    // cp.async staging: chunk c -> buffer buf. 256 rows x 64 floats.
    const int r0  = t >> 4;                   // 0..7
    const int col = (t & 15) * 4;             // 0..60
    const float* gbase = mem + (size_t)bx * AROWS * D_;

#define STAGE(c, buf)  do {                                                        \
        const float* gp = gbase + (size_t)(c)*DC + r0*D_ + col;                    \
        uint32_t sp = sbase + 4u*((buf)*TILEF + r0*PITCH + col);                   \
        _Pragma("unroll")                                                          \
        for (int k = 0; k < 32; ++k)                                               \
            cpa16(sp + 4u*(8*k*PITCH), gp + (size_t)(8*k)*D_);                     \
        asm volatile("cp.async.commit_group;\n" ::: "memory");                     \
    } while (0)

    unsigned long long acc0[L_], acc1[L_];
#pragma unroll
    for (int l = 0; l < L_; ++l) { acc0[l] = 0ULL; acc1[l] = 0ULL; }

    STAGE(0, 0);

    for (int c = 0; c < NCH; ++c) {
        if (c + 1 < NCH) {
            STAGE(c + 1, (c + 1) & 1);
            asm volatile("cp.async.wait_group 1;\n" ::: "memory");
        } else {
            asm volatile("cp.async.wait_group 0;\n" ::: "memory");
        }
        __syncthreads();

        const int buf = c & 1;
        const ulonglong2* r0p = (const ulonglong2*)&sA[buf*TILEF + t*PITCH];
        const ulonglong2* r1p = (const ulonglong2*)&sA[buf*TILEF + (t+128)*PITCH];
        const int cbase = c * DC;

#pragma unroll 4
        for (int j = 0; j < DC/4; ++j) {          // 16 d-groups of 4
            const ulonglong2 m0 = r0p[j];
            const ulonglong2 m1 = r1p[j];
#pragma unroll
            for (int l = 0; l < L_; ++l) {
                // constant port (LDC.128): zero crossbar traffic
                const ulonglong2 sv = *(const ulonglong2*)&c_summ[l*D_ + cbase + 4*j];
                acc0[l] = ffma2(sv.x, m0.x, acc0[l]);
                acc0[l] = ffma2(sv.y, m0.y, acc0[l]);
                acc1[l] = ffma2(sv.x, m1.x, acc1[l]);
                acc1[l] = ffma2(sv.y, m1.y, acc1[l]);
            }
        }
        __syncthreads();
    }

    // epilogue: exp, store e, per-block partial Z
    const int b   = bx >> 4;
    const int sch = (bx & 15) << 8;
    const int wid = t >> 5, lid = t & 31;
    float* wred = &sA[OFF_WR];

#pragma unroll
    for (int l = 0; l < L_; ++l) {
        union { unsigned long long u; float2 f; } c0, c1;
        c0.u = acc0[l]; c1.u = acc1[l];
        float e0 = __expf((c0.f.x + c0.f.y) * 0.03125f);   // scores ~O(0.05): no max sub
        float e1 = __expf((c1.f.x + c1.f.y) * 0.03125f);
        float* ep = g_e + ((size_t)(b*L_ + l) << 12) + sch + t;
        ep[0]   = e0;
        ep[128] = e1;
        float v = e0 + e1;
#pragma unroll
        for (int o = 16; o > 0; o >>= 1) v += __shfl_xor_sync(0xFFFFFFFFu, v, o);
        if (lid == 0) wred[wid*L_ + l] = v;
    }
    __syncthreads();
    if (t < L_) {
        float zp = wred[t] + wred[L_ + t] + wred[2*L_ + t] + wred[3*L_ + t];
        g_zpart[bx*L_ + t] = zp;
    }
#undef STAGE
}

// ---------------------------------------------------------------------------
// Kernel C: c=w/Z, q[s]=sum_l c_l*e_ls, partial out = sum_s q*mem,
//           last block per batch reduces the 32 partials (fixed order).
// 256 CTAs (2/SM), 128 s-rows each, unroll 16 for deep MLP.
// ---------------------------------------------------------------------------
__global__ void __launch_bounds__(256, 2)
kC(const float* __restrict__ mem, const float* __restrict__ wproj,
   float* __restrict__ out) {
    const int t  = threadIdx.x;
    const int bx = blockIdx.x;
    const int b  = bx >> 5;                    // 32 blocks per batch
    const int s0 = (bx & 31) << 7;             // 128 rows per block

    __shared__ float zs[256];
    __shared__ float cs[L_];
    __shared__ float qs[CROWS];
    __shared__ int lastFlag;

    zs[t] = g_zpart[b*256 + t];               // [j=0..15][l=0..15] of this batch
    __syncthreads();
    if (t < L_) {
        float Z = 0.f;
#pragma unroll
        for (int j = 0; j < 16; ++j) Z += zs[j*L_ + t];
        cs[t] = wproj[t] / Z;
    }
    __syncthreads();

    if (t < CROWS) {   // q for this block's 128 s-rows
        const float* ep = g_e + ((size_t)b*L_ << 12) + s0 + t;
        float q = 0.f;
#pragma unroll
        for (int l = 0; l < L_; ++l) q += cs[l] * ep[(size_t)l << 12];
        qs[t] = q;
    }
    __syncthreads();

    // HBM-bound pass: thread owns float4 column t
    const float4* mp = (const float4*)mem + ((size_t)(b*S_ + s0)) * (D_/4) + t;
    float4 a = make_float4(0.f, 0.f, 0.f, 0.f);
#pragma unroll 16
    for (int i = 0; i < CROWS; ++i) {
        float4 m = mp[(size_t)i * (D_/4)];
        float q = qs[i];
        a.x += q*m.x; a.y += q*m.y; a.z += q*m.z; a.w += q*m.w;
    }
    ((float4*)g_part)[bx*(D_/4) + t] = a;

    __threadfence();
    __syncthreads();
    if (t == 0) lastFlag = (atomicAdd(&g_cnt[b], 1) == 31);
    __syncthreads();

    if (lastFlag) {
        __threadfence();
        float4 r = make_float4(0.f, 0.f, 0.f, 0.f);
#pragma unroll
        for (int j = 0; j < 32; ++j) {
            float4 p = ((const float4*)g_part)[(b*32 + j)*(D_/4) + t];
            r.x += p.x; r.y += p.y; r.z += p.z; r.w += p.w;
        }
        ((float4*)out)[b*(D_/4) + t] = r;
    }
}

// ---------------------------------------------------------------------------
extern "C" void kernel_launch(void* const* d_in, const int* in_sizes, int n_in,
                              void* d_out, int out_size) {
    const float* mem = nullptr;
    const float* summ = nullptr;
    const float* w = nullptr;
    for (int i = 0; i < n_in; ++i) {
        if      (in_sizes[i] == B_*S_*D_) mem  = (const float*)d_in[i];
        else if (in_sizes[i] == L_*D_)    summ = (const float*)d_in[i];
        else if (in_sizes[i] == L_)       w    = (const float*)d_in[i];
    }
    static bool attrDone = false;
    if (!attrDone) {
        cudaFuncSetAttribute(kA, cudaFuncAttributeMaxDynamicSharedMemorySize, SMEMA_BYTES);
        attrDone = true;
    }
    cudaMemcpyToSymbolAsync(c_summ, summ, L_*D_*sizeof(float), 0,
                            cudaMemcpyDeviceToDevice, 0);
    kA<<<ABLK, ATHR, SMEMA_BYTES>>>(mem);
    kC<<<CBLK, 256>>>(mem, w, (float*)d_out);
}

// round 4
// speedup vs baseline: 1.7096x; 1.7096x over previous
#include <cuda_runtime.h>
#include <cstdint>

#define B_    8
#define S_    4096
#define D_    1024
#define L_    16

// ---- kernel A geometry ----
#define ABLK  128          // 32768 s-rows / 256
#define AROWS 256          // s-rows per block, 1 per thread
#define ATHR  256
#define DC    64           // d-chunk width
#define NCH   (D_/DC)      // 16 chunks
#define PITCH 68           // padded floats per tile row (16B aligned)
#define TILEF (AROWS*PITCH)          // 17408 floats per buffer
#define SUMMF (L_*D_)                // 16384 floats
#define OFF_SU (2*TILEF)
#define OFF_WR (OFF_SU + SUMMF)
#define SMEMA_BYTES ((OFF_WR + 8*L_) * 4)   // ~205.8 KB

// ---- kernel C geometry ----
#define CBLK  512          // 64 blocks per batch
#define CTHR  128
#define CROWS 64

// device scratch (allocation-free rule)
__device__ float g_e[B_*L_*S_];        // exp(scores)   2 MB
__device__ float g_zpart[ABLK*L_];     // per-A-block partial Z
__device__ float g_part[CBLK*D_];      // per-C-block partial ctx (2 MB)
__device__ int   g_cnt[B_];            // arrival counters (reset by kernel A)

__device__ __forceinline__ unsigned long long ffma2(unsigned long long a,
                                                    unsigned long long b,
                                                    unsigned long long c) {
    unsigned long long d;
    asm("fma.rn.f32x2 %0, %1, %2, %3;" : "=l"(d) : "l"(a), "l"(b), "l"(c));
    return d;
}

__device__ __forceinline__ void cpa16(uint32_t saddr, const void* gaddr) {
    asm volatile("cp.async.ca.shared.global [%0], [%1], 16;\n" :: "r"(saddr), "l"(gaddr));
}

// ---------------------------------------------------------------------------
// Kernel A: e[b,l,s] = exp( dot(summ[l], mem[b,s]) / 32 )  + per-block Z partials
// 256 threads, 1 s-row each; summarizer in smem (broadcast LDS.128);
// m tile double-buffered via cp.async; K packed into f32x2 FMAs.
// ---------------------------------------------------------------------------
__global__ void __launch_bounds__(ATHR, 1)
kA(const float* __restrict__ mem, const float* __restrict__ summ) {
    extern __shared__ float sA[];
    const int t   = threadIdx.x;
    const int bx  = blockIdx.x;
    const uint32_t sbase = (uint32_t)__cvta_generic_to_shared(sA);

    if (bx < B_ && t == 0) g_cnt[bx] = 0;     // reset kernel-C counters each launch

    // stage full summarizer -> smem (coalesced float4)
    {
        const float4* sg = (const float4*)summ;
        float4* ss = (float4*)&sA[OFF_SU];
#pragma unroll
        for (int k = 0; k < SUMMF/4/ATHR; ++k)       // 16 float4 per thread
            ss[k*ATHR + t] = sg[k*ATHR + t];
    }

    // cp.async staging: chunk c -> buffer buf. 256 rows x 64 floats.
    const int r0  = t >> 4;                   // 0..15
    const int col = (t & 15) * 4;             // 0..60
    const float* gbase = mem + (size_t)bx * AROWS * D_;

#define STAGE(c, buf)  do {                                                        \
        const float* gp = gbase + (size_t)(c)*DC + r0*D_ + col;                    \
        uint32_t sp = sbase + 4u*((buf)*TILEF + r0*PITCH + col);                   \
        _Pragma("unroll")                                                          \
        for (int k = 0; k < 16; ++k)                                               \
            cpa16(sp + 4u*(16*k*PITCH), gp + (size_t)(16*k)*D_);                   \
        asm volatile("cp.async.commit_group;\n" ::: "memory");                     \
    } while (0)

    unsigned long long acc[L_];
#pragma unroll
    for (int l = 0; l < L_; ++l) acc[l] = 0ULL;

    STAGE(0, 0);

    for (int c = 0; c < NCH; ++c) {
        if (c + 1 < NCH) {
            STAGE(c + 1, (c + 1) & 1);
            asm volatile("cp.async.wait_group 1;\n" ::: "memory");
        } else {
            asm volatile("cp.async.wait_group 0;\n" ::: "memory");
        }
        __syncthreads();

        const int buf = c & 1;
        const ulonglong2* rp = (const ulonglong2*)&sA[buf*TILEF + t*PITCH];
        const ulonglong2* sp = (const ulonglong2*)&sA[OFF_SU + c*DC];

#pragma unroll 4
        for (int j = 0; j < DC/4; ++j) {          // 16 d-groups of 4
            const ulonglong2 m = rp[j];
#pragma unroll
            for (int l = 0; l < L_; ++l) {
                const ulonglong2 sv = sp[l*(D_/4) + j];   // broadcast LDS.128
                acc[l] = ffma2(sv.x, m.x, acc[l]);
                acc[l] = ffma2(sv.y, m.y, acc[l]);
            }
        }
        __syncthreads();
    }

    // epilogue: exp, store e, per-block partial Z
    const int b   = bx >> 4;
    const int sch = (bx & 15) << 8;
    const int wid = t >> 5, lid = t & 31;
    float* wred = &sA[OFF_WR];                // 8 warps x 16 l

#pragma unroll
    for (int l = 0; l < L_; ++l) {
        union { unsigned long long u; float2 f; } cv; cv.u = acc[l];
        float e0 = __expf((cv.f.x + cv.f.y) * 0.03125f);   // scores O(0.05): no max sub
        g_e[((size_t)(b*L_ + l) << 12) + sch + t] = e0;
        float v = e0;
#pragma unroll
        for (int o = 16; o > 0; o >>= 1) v += __shfl_xor_sync(0xFFFFFFFFu, v, o);
        if (lid == 0) wred[wid*L_ + l] = v;
    }
    __syncthreads();
    if (t < L_) {
        float zp = 0.f;
#pragma unroll
        for (int w = 0; w < 8; ++w) zp += wred[w*L_ + t];
        g_zpart[bx*L_ + t] = zp;
    }
#undef STAGE
}

// ---------------------------------------------------------------------------
// Kernel C: c=w/Z, q[s]=sum_l c_l*e_ls, partial out = sum_s q*mem,
//           last block per batch reduces the 64 partials (fixed order).
// 512 CTAs x 128 threads, 64 s-rows each -> high MLP, DRAM-bound.
// ---------------------------------------------------------------------------
__global__ void __launch_bounds__(CTHR, 6)
kC(const float* __restrict__ mem, const float* __restrict__ wproj,
   float* __restrict__ out) {
    const int t  = threadIdx.x;
    const int bx = blockIdx.x;
    const int b  = bx >> 6;                    // 64 blocks per batch
    const int s0 = (bx & 63) << 6;             // 64 rows per block

    __shared__ float zs[256];
    __shared__ float cs[L_];
    __shared__ float qs[CROWS];
    __shared__ int lastFlag;

    zs[t]       = g_zpart[b*256 + t];          // 16 A-blocks x 16 l for batch b
    zs[t + 128] = g_zpart[b*256 + t + 128];
    __syncthreads();
    if (t < L_) {
        float Z = 0.f;
#pragma unroll
        for (int j = 0; j < 16; ++j) Z += zs[j*L_ + t];
        cs[t] = wproj[t] / Z;
    }
    __syncthreads();

    if (t < CROWS) {   // q for this block's 64 s-rows
        const float* ep = g_e + ((size_t)b*L_ << 12) + s0 + t;
        float q = 0.f;
#pragma unroll
        for (int l = 0; l < L_; ++l) q += cs[l] * ep[(size_t)l << 12];
        qs[t] = q;
    }
    __syncthreads();

    // HBM-bound pass: thread owns float4 columns t and t+128
    const float4* mp = (const float4*)mem + ((size_t)(b*S_ + s0)) * (D_/4);
    float4 a0 = make_float4(0.f, 0.f, 0.f, 0.f);
    float4 a1 = make_float4(0.f, 0.f, 0.f, 0.f);
#pragma unroll 8
    for (int i = 0; i < CROWS; ++i) {
        float4 m0 = mp[(size_t)i * (D_/4) + t];
        float4 m1 = mp[(size_t)i * (D_/4) + t + 128];
        float q = qs[i];
        a0.x += q*m0.x; a0.y += q*m0.y; a0.z += q*m0.z; a0.w += q*m0.w;
        a1.x += q*m1.x; a1.y += q*m1.y; a1.z += q*m1.z; a1.w += q*m1.w;
    }
    ((float4*)g_part)[(size_t)bx*(D_/4) + t]       = a0;
    ((float4*)g_part)[(size_t)bx*(D_/4) + t + 128] = a1;

    __threadfence();
    __syncthreads();
    if (t == 0) lastFlag = (atomicAdd(&g_cnt[b], 1) == 63);
    __syncthreads();

    if (lastFlag) {
        __threadfence();
        float4 r0 = make_float4(0.f, 0.f, 0.f, 0.f);
        float4 r1 = make_float4(0.f, 0.f, 0.f, 0.f);
#pragma unroll
        for (int j = 0; j < 64; ++j) {
            float4 p0 = ((const float4*)g_part)[(size_t)(b*64 + j)*(D_/4) + t];
            float4 p1 = ((const float4*)g_part)[(size_t)(b*64 + j)*(D_/4) + t + 128];
            r0.x += p0.x; r0.y += p0.y; r0.z += p0.z; r0.w += p0.w;
            r1.x += p1.x; r1.y += p1.y; r1.z += p1.z; r1.w += p1.w;
        }
        ((float4*)out)[b*(D_/4) + t]       = r0;
        ((float4*)out)[b*(D_/4) + t + 128] = r1;
    }
}

// ---------------------------------------------------------------------------
extern "C" void kernel_launch(void* const* d_in, const int* in_sizes, int n_in,
                              void* d_out, int out_size) {
    const float* mem = nullptr;
    const float* summ = nullptr;
    const float* w = nullptr;
    for (int i = 0; i < n_in; ++i) {
        if      (in_sizes[i] == B_*S_*D_) mem  = (const float*)d_in[i];
        else if (in_sizes[i] == L_*D_)    summ = (const float*)d_in[i];
        else if (in_sizes[i] == L_)       w    = (const float*)d_in[i];
    }
    static bool attrDone = false;
    if (!attrDone) {
        cudaFuncSetAttribute(kA, cudaFuncAttributeMaxDynamicSharedMemorySize, SMEMA_BYTES);
        attrDone = true;
    }
    kA<<<ABLK, ATHR, SMEMA_BYTES>>>(mem, summ);
    kC<<<CBLK, CTHR>>>(mem, w, (float*)d_out);
}

// round 5
// speedup vs baseline: 3.6320x; 2.1245x over previous
#include <cuda_runtime.h>
#include <cstdint>

#define B_    8
#define S_    4096
#define D_    1024
#define L_    16

// ---- kernel A geometry ----
#define ABLK   128         // 32768 s-rows / 256
#define AROWS  256         // s-rows per block
#define ATHR   256         // 8 warps, each owns 32 s-rows
#define DC     64          // d-chunk width
#define NCH    (D_/DC)     // 16 chunks
#define PITCH  68          // tile row pitch (floats): (4r+k) mod 32 distinct -> conflict-free
#define TILEF  (AROWS*PITCH)            // 17408 floats per buffer
#define SPITCH 1028        // summ row pitch: (4l+k) mod 32 distinct
#define EPITCH 264         // score staging pitch
#define OFF_SU (2*TILEF)                      // 34816
#define OFF_ES (OFF_SU + L_*SPITCH)           // 51264
#define OFF_WR (OFF_ES + L_*EPITCH)           // 55488
#define SMEMA_FLOATS (OFF_WR + 8*L_)
#define SMEMA_BYTES  (SMEMA_FLOATS*4)         // ~222.5 KB

// ---- kernel C geometry (R3 measured-best config) ----
#define CBLK  256
#define CTHR  256
#define CROWS 128

// device scratch (allocation-free rule)
__device__ float g_e[B_*L_*S_];        // exp(scores)   2 MB
__device__ float g_zpart[ABLK*L_];     // per-A-block partial Z
__device__ float g_part[CBLK*D_];      // per-C-block partial ctx
__device__ int   g_cnt[B_];            // arrival counters (reset by kernel A)

__device__ __forceinline__ void cpa16(uint32_t saddr, const void* gaddr) {
    asm volatile("cp.async.ca.shared.global [%0], [%1], 16;\n" :: "r"(saddr), "l"(gaddr));
}

__device__ __forceinline__ void mma_tf32(float* c, const float* a, const float* b) {
    asm volatile(
        "mma.sync.aligned.m16n8k8.row.col.f32.tf32.tf32.f32 "
        "{%0,%1,%2,%3}, {%4,%5,%6,%7}, {%8,%9}, {%0,%1,%2,%3};\n"
        : "+f"(c[0]), "+f"(c[1]), "+f"(c[2]), "+f"(c[3])
        : "f"(a[0]), "f"(a[1]), "f"(a[2]), "f"(a[3]),
          "f"(b[0]), "f"(b[1]));
}

// ---------------------------------------------------------------------------
// Kernel A: e[b,l,s] = exp( dot(summ[l], mem[b,s]) / 32 )  + per-block Z partials.
// Tensor-core scores: A = summ (16 x 1024, tf32), B = mem tile (s x d)^T.
// mem tile double-buffered via cp.async; warp w owns s-rows [32w, 32w+32).
// ---------------------------------------------------------------------------
__global__ void __launch_bounds__(ATHR, 1)
kA(const float* __restrict__ mem, const float* __restrict__ summ) {
    extern __shared__ float sA[];
    const int t    = threadIdx.x;
    const int bx   = blockIdx.x;
    const int warp = t >> 5;
    const int lane = t & 31;
    const int g    = lane >> 2;      // group id
    const int tig  = lane & 3;       // thread-in-group
    const uint32_t sbase = (uint32_t)__cvta_generic_to_shared(sA);

    if (bx < B_ && t == 0) g_cnt[bx] = 0;     // reset kernel-C counters each launch

    // stage summarizer -> padded smem
    for (int i = t; i < L_*D_; i += ATHR) {
        int l = i >> 10, j = i & 1023;
        sA[OFF_SU + l*SPITCH + j] = summ[i];
    }

    // cp.async staging: chunk c -> buffer buf. 256 rows x 64 floats.
    const int r0  = t >> 4;                   // 0..15
    const int col = (t & 15) * 4;             // 0..60
    const float* gbase = mem + (size_t)bx * AROWS * D_;

#define STAGE(c, buf)  do {                                                        \
        const float* gp = gbase + (size_t)(c)*DC + r0*D_ + col;                    \
        uint32_t sp = sbase + 4u*((buf)*TILEF + r0*PITCH + col);                   \
        _Pragma("unroll")                                                          \
        for (int k = 0; k < 16; ++k)                                               \
            cpa16(sp + 4u*(16*k*PITCH), gp + (size_t)(16*k)*D_);                   \
        asm volatile("cp.async.commit_group;\n" ::: "memory");                     \
    } while (0)

    float acc[4][4];                 // 4 n-tiles x c[4]
#pragma unroll
    for (int nt = 0; nt < 4; ++nt)
#pragma unroll
        for (int i = 0; i < 4; ++i) acc[nt][i] = 0.f;

    const int s0w = warp * 32;       // warp's s base within tile

    STAGE(0, 0);

    for (int c = 0; c < NCH; ++c) {
        if (c + 1 < NCH) {
            STAGE(c + 1, (c + 1) & 1);
            asm volatile("cp.async.wait_group 1;\n" ::: "memory");
        } else {
            asm volatile("cp.async.wait_group 0;\n" ::: "memory");
        }
        __syncthreads();

        const float* tile = &sA[(c & 1) * TILEF];
        const int kg = c * DC;       // global k base of this chunk

#pragma unroll
        for (int ks = 0; ks < DC/8; ++ks) {       // 8 k-steps of K=8
            const int kk = ks * 8;                // chunk-local
            float a[4];
            a[0] = sA[OFF_SU + g*SPITCH       + kg + kk + tig];
            a[1] = sA[OFF_SU + (g+8)*SPITCH   + kg + kk + tig];
            a[2] = sA[OFF_SU + g*SPITCH       + kg + kk + tig + 4];
            a[3] = sA[OFF_SU + (g+8)*SPITCH   + kg + kk + tig + 4];
#pragma unroll
            for (int nt = 0; nt < 4; ++nt) {
                const int srow = s0w + nt*8 + g;
                float b[2];
                b[0] = tile[srow*PITCH + kk + tig];
                b[1] = tile[srow*PITCH + kk + tig + 4];
                mma_tf32(acc[nt], a, b);
            }
        }
        __syncthreads();
    }

    // write C frags to score staging smem: escore[l][s_local]
    float* es = &sA[OFF_ES];
#pragma unroll
    for (int nt = 0; nt < 4; ++nt) {
        const int n0 = s0w + nt*8 + 2*tig;
        *(float2*)&es[ g     *EPITCH + n0] = make_float2(acc[nt][0], acc[nt][1]);
        *(float2*)&es[(g+8)  *EPITCH + n0] = make_float2(acc[nt][2], acc[nt][3]);
    }
    __syncthreads();

    // epilogue: exp, store e, per-block partial Z
    const int b   = bx >> 4;
    const int sch = (bx & 15) << 8;
    float* wred = &sA[OFF_WR];                // 8 warps x 16 l

#pragma unroll
    for (int l = 0; l < L_; ++l) {
        float e0 = __expf(es[l*EPITCH + t] * 0.03125f);  // /sqrt(1024); scores O(0.05)
        g_e[((size_t)(b*L_ + l) << 12) + sch + t] = e0;
        float v = e0;
#pragma unroll
        for (int o = 16; o > 0; o >>= 1) v += __shfl_xor_sync(0xFFFFFFFFu, v, o);
        if (lane == 0) wred[warp*L_ + l] = v;
    }
    __syncthreads();
    if (t < L_) {
        float zp = 0.f;
#pragma unroll
        for (int w = 0; w < 8; ++w) zp += wred[w*L_ + t];
        g_zpart[bx*L_ + t] = zp;
    }
#undef STAGE
}

// ---------------------------------------------------------------------------
// Kernel C (R3 measured-best): c=w/Z, q, partial ctx, last-block reduce.
// ---------------------------------------------------------------------------
__global__ void __launch_bounds__(CTHR, 2)
kC(const float* __restrict__ mem, const float* __restrict__ wproj,
   float* __restrict__ out) {
    const int t  = threadIdx.x;
    const int bx = blockIdx.x;
    const int b  = bx >> 5;                    // 32 blocks per batch
    const int s0 = (bx & 31) << 7;             // 128 rows per block

    __shared__ float zs[256];
    __shared__ float cs[L_];
    __shared__ float qs[CROWS];
    __shared__ int lastFlag;

    zs[t] = g_zpart[b*256 + t];               // 16 A-blocks x 16 l of this batch
    __syncthreads();
    if (t < L_) {
        float Z = 0.f;
#pragma unroll
        for (int j = 0; j < 16; ++j) Z += zs[j*L_ + t];
        cs[t] = wproj[t] / Z;
    }
    __syncthreads();

    if (t < CROWS) {   // q for this block's 128 s-rows
        const float* ep = g_e + ((size_t)b*L_ << 12) + s0 + t;
        float q = 0.f;
#pragma unroll
        for (int l = 0; l < L_; ++l) q += cs[l] * ep[(size_t)l << 12];
        qs[t] = q;
    }
    __syncthreads();

    // HBM-bound pass: thread owns float4 column t
    const float4* mp = (const float4*)mem + ((size_t)(b*S_ + s0)) * (D_/4) + t;
    float4 a = make_float4(0.f, 0.f, 0.f, 0.f);
#pragma unroll 16
    for (int i = 0; i < CROWS; ++i) {
        float4 m = mp[(size_t)i * (D_/4)];
        float q = qs[i];
        a.x += q*m.x; a.y += q*m.y; a.z += q*m.z; a.w += q*m.w;
    }
    ((float4*)g_part)[bx*(D_/4) + t] = a;

    __threadfence();
    __syncthreads();
    if (t == 0) lastFlag = (atomicAdd(&g_cnt[b], 1) == 31);
    __syncthreads();

    if (lastFlag) {
        __threadfence();
        float4 r = make_float4(0.f, 0.f, 0.f, 0.f);
#pragma unroll
        for (int j = 0; j < 32; ++j) {
            float4 p = ((const float4*)g_part)[(b*32 + j)*(D_/4) + t];
            r.x += p.x; r.y += p.y; r.z += p.z; r.w += p.w;
        }
        ((float4*)out)[b*(D_/4) + t] = r;
    }
}

// ---------------------------------------------------------------------------
extern "C" void kernel_launch(void* const* d_in, const int* in_sizes, int n_in,
                              void* d_out, int out_size) {
    const float* mem = nullptr;
    const float* summ = nullptr;
    const float* w = nullptr;
    for (int i = 0; i < n_in; ++i) {
        if      (in_sizes[i] == B_*S_*D_) mem  = (const float*)d_in[i];
        else if (in_sizes[i] == L_*D_)    summ = (const float*)d_in[i];
        else if (in_sizes[i] == L_)       w    = (const float*)d_in[i];
    }
    static bool attrDone = false;
    if (!attrDone) {
        cudaFuncSetAttribute(kA, cudaFuncAttributeMaxDynamicSharedMemorySize, SMEMA_BYTES);
        attrDone = true;
    }
    kA<<<ABLK, ATHR, SMEMA_BYTES>>>(mem, summ);
    kC<<<CBLK, CTHR>>>(mem, w, (float*)d_out);
}